// round 11
// baseline (speedup 1.0000x reference)
#include <cuda_runtime.h>
#include <cstdint>

// Per-row stream compaction:
//   x3: [B*C, L] f32, L=16384. Drop entries exactly equal to 10.1f, keep
//   order, emit first KEEP=12288 survivors per row. Setup guarantees exactly
//   L-KEEP fillers per row, so output is fully written.
//
// R6: keep the R5 smem-staging scatter, replace the per-thread float4 drain
// (3 LDS.128 + 3 STG.128/thread = ~24 L1 wavefronts/warp) with a single
// 49152-byte TMA 1D bulk store (cp.async.bulk.global.shared::cta) issued by
// one elected thread per CTA. Drain bytes move off the L1 per-thread path
// onto the TMA engine; L1 was the binding unit at 67.2%.

#define FILLER 10.1f

constexpr int L_DIM   = 16384;
constexpr int KEEP    = 12288;
constexpr int THREADS = 1024;
constexpr int PER_T   = L_DIM / THREADS;    // 16 elements per thread
constexpr int VEC     = PER_T / 4;          // 4 float4 loads per thread

__global__ __launch_bounds__(THREADS, 2)
void compact_rows_kernel(const float* __restrict__ x3,
                         float* __restrict__ out,
                         int n_rows)
{
    extern __shared__ __align__(16) float stage[]; // KEEP floats = 49152 B dynamic
    int* warp_sums = reinterpret_cast<int*>(stage); // transient reuse

    const int row = blockIdx.x;
    if (row >= n_rows) return;

    const float* __restrict__ in = x3 + (size_t)row * L_DIM;
    float* __restrict__ o        = out + (size_t)row * KEEP;

    const int tid  = threadIdx.x;
    const int lane = tid & 31;
    const int wid  = tid >> 5;

    // Each thread owns a contiguous run of 16 elements (order preservation).
    float v[PER_T];
    const float4* __restrict__ in4 =
        reinterpret_cast<const float4*>(in + tid * PER_T);
#pragma unroll
    for (int j = 0; j < VEC; ++j) {
        float4 t = in4[j];
        v[4 * j + 0] = t.x;
        v[4 * j + 1] = t.y;
        v[4 * j + 2] = t.z;
        v[4 * j + 3] = t.w;
    }

    // Survivor count for this thread.
    int c = 0;
#pragma unroll
    for (int i = 0; i < PER_T; ++i) c += (v[i] != FILLER) ? 1 : 0;

    // Warp-level inclusive scan of counts.
    int inc = c;
#pragma unroll
    for (int d = 1; d < 32; d <<= 1) {
        int y = __shfl_up_sync(0xFFFFFFFFu, inc, d);
        if (lane >= d) inc += y;
    }

    // Block-level scan of warp totals (32 warps) held in stage[0..31].
    if (lane == 31) warp_sums[wid] = inc;
    __syncthreads();
    if (wid == 0) {
        int s = warp_sums[lane];
#pragma unroll
        for (int d = 1; d < 32; d <<= 1) {
            int y = __shfl_up_sync(0xFFFFFFFFu, s, d);
            if (lane >= d) s += y;
        }
        warp_sums[lane] = s;   // inclusive over warps <= lane
    }
    __syncthreads();

    const int off0 = (wid > 0 ? warp_sums[wid - 1] : 0) + (inc - c);

    // All reads of warp_sums must retire before the scatter overwrites
    // stage[0..31].
    __syncthreads();

    // Ordered scatter of survivors into the shared staging buffer.
    int off = off0;
#pragma unroll
    for (int i = 0; i < PER_T; ++i) {
        if (v[i] != FILLER) {
            if (off < KEEP) stage[off] = v[i];
            ++off;
        }
    }
    __syncthreads();

    // TMA 1D bulk-store drain: one 49152-byte smem -> gmem copy per CTA.
    if (tid == 0) {
        uint32_t s_addr;
        asm("{ .reg .u64 t; cvta.to.shared.u64 t, %1; cvt.u32.u64 %0, t; }"
            : "=r"(s_addr) : "l"(stage));
        // Order the generic-proxy STS scatter before the async-proxy read.
        asm volatile("fence.proxy.async.shared::cta;" ::: "memory");
        asm volatile(
            "cp.async.bulk.global.shared::cta.bulk_group [%0], [%1], %2;"
            :: "l"(o), "r"(s_addr), "r"((int)(KEEP * sizeof(float)))
            : "memory");
        asm volatile("cp.async.bulk.commit_group;" ::: "memory");
        // Keep the CTA (and its smem) alive until TMA has consumed the data.
        asm volatile("cp.async.bulk.wait_group 0;" ::: "memory");
    }
}

extern "C" void kernel_launch(void* const* d_in, const int* in_sizes, int n_in,
                              void* d_out, int out_size)
{
    // metadata order: x1 [B,C,4096] f32, x2 [B,C,4096] f32,
    //                 x3 [B,C,16384] f32, keep_len (int scalar)
    const float* x3 = (const float*)d_in[2];
    float* out = (float*)d_out;

    const int n_rows = in_sizes[2] / L_DIM;            // B*C = 2048
    const int smem_bytes = KEEP * (int)sizeof(float);  // 49152 B = 48 KB

    compact_rows_kernel<<<n_rows, THREADS, smem_bytes>>>(x3, out, n_rows);
}

// round 13
// speedup vs baseline: 1.3057x; 1.3057x over previous
#include <cuda_runtime.h>
#include <cstdint>

// Per-row stream compaction:
//   x3: [B*C, L] f32, L=16384. Drop entries exactly equal to 10.1f, keep
//   order, emit first KEEP=12288 survivors per row. Setup guarantees exactly
//   L-KEEP fillers per row, so output is fully written.
//
// R7: revert the TMA drain (R6 regression: CTA-lifetime tail, tma pipe idle).
// Keep R5 smem staging + coalesced float4 drain, but TRANSPOSE intra-warp
// ownership: warp w owns contiguous chunk [512w, 512w+512); thread t owns
// float4s at chunk + 128*i + 4*t, i=0..3. Input order == (i, t, k) lex
// order, so per-round dense emission preserves order while making scatter
// STS addresses advance ~3 words/lane (gcd(3,32)=1, near conflict-free)
// instead of ~12 (4-way conflicts). All 4 per-round lane scans fused into
// ONE 5-shfl scan over byte-packed counts.

#define FILLER 10.1f

constexpr int L_DIM   = 16384;
constexpr int KEEP    = 12288;
constexpr int THREADS = 1024;               // 32 warps
constexpr int CHUNK   = 512;                // elements per warp
constexpr int ROUNDS  = 4;                  // float4 rounds per thread
constexpr int OUT_V4  = KEEP / 4 / THREADS; // 3 float4 stores per thread

__global__ __launch_bounds__(THREADS, 2)
void compact_rows_kernel(const float* __restrict__ x3,
                         float* __restrict__ out,
                         int n_rows)
{
    extern __shared__ __align__(16) float stage[]; // KEEP floats = 49152 B
    int* warp_sums = reinterpret_cast<int*>(stage); // transient reuse

    const int row = blockIdx.x;
    if (row >= n_rows) return;

    const float* __restrict__ in = x3 + (size_t)row * L_DIM;
    float* __restrict__ o        = out + (size_t)row * KEEP;

    const int tid  = threadIdx.x;
    const int lane = tid & 31;
    const int wid  = tid >> 5;

    // Warp-contiguous chunk; thread t owns float4 at chunk + 128*i + 4*t.
    const float4* __restrict__ in4 =
        reinterpret_cast<const float4*>(in + wid * CHUNK);

    float4 q[ROUNDS];
#pragma unroll
    for (int i = 0; i < ROUNDS; ++i)
        q[i] = in4[i * 32 + lane];

    // Per-round survivor counts, byte-packed (each byte <= 4; scan sums <= 128).
    unsigned packed = 0;
    int      c[ROUNDS];
#pragma unroll
    for (int i = 0; i < ROUNDS; ++i) {
        int ci = (q[i].x != FILLER) + (q[i].y != FILLER) +
                 (q[i].z != FILLER) + (q[i].w != FILLER);
        c[i] = ci;
        packed |= (unsigned)ci << (8 * i);
    }

    // One SIMD warp scan covers all 4 rounds' lane prefixes.
    unsigned incp = packed;
#pragma unroll
    for (int d = 1; d < 32; d <<= 1) {
        unsigned y = __shfl_up_sync(0xFFFFFFFFu, incp, d);
        if (lane >= d) incp += y;
    }
    const unsigned tot = __shfl_sync(0xFFFFFFFFu, incp, 31); // warp totals/round

    const int t0 = tot & 0xFF, t1 = (tot >> 8) & 0xFF,
              t2 = (tot >> 16) & 0xFF, t3 = (tot >> 24) & 0xFF;
    const int warp_total = t0 + t1 + t2 + t3;

    // Block scan of warp totals (32 warps) in stage[0..31].
    if (lane == 0) warp_sums[wid] = warp_total;
    __syncthreads();
    if (wid == 0) {
        int s = warp_sums[lane];
#pragma unroll
        for (int d = 1; d < 32; d <<= 1) {
            int y = __shfl_up_sync(0xFFFFFFFFu, s, d);
            if (lane >= d) s += y;
        }
        warp_sums[lane] = s;   // inclusive over warps <= lane
    }
    __syncthreads();
    const int warp_base = (wid > 0 ? warp_sums[wid - 1] : 0);

    // Reads of warp_sums must retire before scatter overwrites stage[0..31].
    __syncthreads();

    // Round bases within the warp's dense output run.
    int B[ROUNDS];
    B[0] = 0; B[1] = t0; B[2] = t0 + t1; B[3] = t0 + t1 + t2;

    // Dense ordered scatter: round i, lane t writes at
    // warp_base + B[i] + (exclusive lane prefix of round i) + quad prefix.
#pragma unroll
    for (int i = 0; i < ROUNDS; ++i) {
        int excl = (int)((incp >> (8 * i)) & 0xFF) - c[i];
        int off  = warp_base + B[i] + excl;
        const float4 t = q[i];
        if (t.x != FILLER) { if (off < KEEP) stage[off] = t.x; ++off; }
        if (t.y != FILLER) { if (off < KEEP) stage[off] = t.y; ++off; }
        if (t.z != FILLER) { if (off < KEEP) stage[off] = t.z; ++off; }
        if (t.w != FILLER) { if (off < KEEP) stage[off] = t.w; ++off; }
    }
    __syncthreads();

    // Coalesced float4 drain: smem -> global.
    float4* __restrict__ o4 = reinterpret_cast<float4*>(o);
    const float4* __restrict__ s4 = reinterpret_cast<const float4*>(stage);
#pragma unroll
    for (int k = 0; k < OUT_V4; ++k) {
        o4[tid + k * THREADS] = s4[tid + k * THREADS];
    }
}

extern "C" void kernel_launch(void* const* d_in, const int* in_sizes, int n_in,
                              void* d_out, int out_size)
{
    // metadata order: x1 [B,C,4096] f32, x2 [B,C,4096] f32,
    //                 x3 [B,C,16384] f32, keep_len (int scalar)
    const float* x3 = (const float*)d_in[2];
    float* out = (float*)d_out;

    const int n_rows = in_sizes[2] / L_DIM;            // B*C = 2048
    const int smem_bytes = KEEP * (int)sizeof(float);  // 49152 B = 48 KB

    compact_rows_kernel<<<n_rows, THREADS, smem_bytes>>>(x3, out, n_rows);
}